// round 8
// baseline (speedup 1.0000x reference)
#include <cuda_runtime.h>
#include <cuda_bf16.h>
#include <math.h>

// Problem: MAB_37409165148591
// B=4, LQ=LK=2048, D=512, H=8, head_dim=64
// out = LN1( T + relu(T@Wo+bo) ),  T = LN0( Q + Attn(Q@Wq+bq, K@Wk+bk, K@Wv+bv, pad_mask) )

#define NB 4
#define LQ 2048
#define LK 2048
#define DM 512
#define NH 8
#define HD 64
#define NROWS (NB * LQ)          // 8192
#define NEL   (NROWS * DM)       // 4194304

typedef unsigned long long ull;

// ---- packed dual-fp32 helpers (sm_103a f32x2 pipe; ptxas won't auto-fuse) ----
__device__ __forceinline__ ull pack2(float x, float y) {
    ull r; asm("mov.b64 %0, {%1,%2};" : "=l"(r) : "f"(x), "f"(y)); return r;
}
__device__ __forceinline__ void fma2(ull& d, ull a, ull b) {
    asm("fma.rn.f32x2 %0, %1, %2, %0;" : "+l"(d) : "l"(a), "l"(b));
}
__device__ __forceinline__ void mul2(ull& d, ull a) {
    asm("mul.rn.f32x2 %0, %0, %1;" : "+l"(d) : "l"(a));
}
__device__ __forceinline__ float2 unpack2(ull v) {
    float2 r; asm("mov.b64 {%0,%1}, %2;" : "=f"(r.x), "=f"(r.y) : "l"(v)); return r;
}

// ---- scratch (static device globals; no allocation allowed) ----
__device__ float g_Qh[NEL];
__device__ float g_Kh[NEL];
__device__ float g_Vh[NEL];
__device__ float g_At[NEL];

// ============================================================================
// GEMM body: C[8192,512] = A[8192,512] @ W[512,512] + bias,
// optional (res + relu(.)). 128x128 tile, BK=16, 256 threads, 8x8 micro-tile,
// f32x2 FMAs. Double-buffered smem: ONE __syncthreads per k-block
// (ldg next -> compute cur -> sts other -> bar). Static smem 33.3KB.
// ============================================================================
template<bool RELU_ADD>
__device__ __forceinline__
void gemm_body(const float* __restrict__ A, const float* __restrict__ W,
               const float* __restrict__ bias, const float* __restrict__ Rp,
               float* __restrict__ C, int n0, int m0)
{
    __shared__ float As[2][16][132];   // [stage][k][m]; 528B row -> 16B-aligned
    __shared__ float Bs[2][16][128];   // [stage][k][n]

    const int tid = threadIdx.x;
    const int tx = tid & 15, ty = tid >> 4;

    const int a_row0 = tid >> 2,           a_c4 = (tid & 3) << 2;
    const int a_row1 = (tid + 256) >> 2;
    const int b_k0 = tid >> 5,             b_n4 = (tid & 31) << 2;
    const int b_k1 = (tid + 256) >> 5;

    const float* Arow0 = A + (size_t)(m0 + a_row0) * DM + a_c4;
    const float* Arow1 = A + (size_t)(m0 + a_row1) * DM + a_c4;
    const float* Wrow0 = W + (size_t)b_k0 * DM + n0 + b_n4;
    const float* Wrow1 = W + (size_t)b_k1 * DM + n0 + b_n4;

    ull acc2[8][4];
#pragma unroll
    for (int i = 0; i < 8; i++)
#pragma unroll
        for (int p = 0; p < 4; p++) acc2[i][p] = 0ull;

    // prologue: block 0 -> regs -> stage 0
    float4 ra0 = *(const float4*)(Arow0);
    float4 ra1 = *(const float4*)(Arow1);
    float4 rb0 = *(const float4*)(Wrow0);
    float4 rb1 = *(const float4*)(Wrow1);
    As[0][a_c4 + 0][a_row0] = ra0.x; As[0][a_c4 + 1][a_row0] = ra0.y;
    As[0][a_c4 + 2][a_row0] = ra0.z; As[0][a_c4 + 3][a_row0] = ra0.w;
    As[0][a_c4 + 0][a_row1] = ra1.x; As[0][a_c4 + 1][a_row1] = ra1.y;
    As[0][a_c4 + 2][a_row1] = ra1.z; As[0][a_c4 + 3][a_row1] = ra1.w;
    *(float4*)&Bs[0][b_k0][b_n4] = rb0;
    *(float4*)&Bs[0][b_k1][b_n4] = rb1;
    __syncthreads();

#pragma unroll 1
    for (int blk = 0; blk < DM / 16; blk++) {
        const int cur = blk & 1;
        const int nxt = cur ^ 1;
        const int kb_next = (blk + 1) * 16;

        // issue next block's LDGs first (latency overlaps compute below)
        if (kb_next < DM) {
            ra0 = *(const float4*)(Arow0 + kb_next);
            ra1 = *(const float4*)(Arow1 + kb_next);
            rb0 = *(const float4*)(Wrow0 + (size_t)kb_next * DM);
            rb1 = *(const float4*)(Wrow1 + (size_t)kb_next * DM);
        }

#pragma unroll
        for (int k = 0; k < 16; k++) {
            float4 a0 = *(const float4*)&As[cur][k][ty << 2];
            float4 a1 = *(const float4*)&As[cur][k][(ty << 2) + 64];
            const ull* bp0 = (const ull*)&Bs[cur][k][tx << 2];
            const ull* bp1 = (const ull*)&Bs[cur][k][(tx << 2) + 64];
            ull b2[4] = {bp0[0], bp0[1], bp1[0], bp1[1]};
            float av[8] = {a0.x, a0.y, a0.z, a0.w, a1.x, a1.y, a1.z, a1.w};
#pragma unroll
            for (int i = 0; i < 8; i++) {
                ull a2 = pack2(av[i], av[i]);
                fma2(acc2[i][0], a2, b2[0]);
                fma2(acc2[i][1], a2, b2[1]);
                fma2(acc2[i][2], a2, b2[2]);
                fma2(acc2[i][3], a2, b2[3]);
            }
        }

        // stage next block into the other buffer; one barrier per iteration.
        // Safe: the buffer being overwritten was last READ in iteration blk-1,
        // and every thread passed the barrier at the end of that iteration.
        if (kb_next < DM) {
            As[nxt][a_c4 + 0][a_row0] = ra0.x; As[nxt][a_c4 + 1][a_row0] = ra0.y;
            As[nxt][a_c4 + 2][a_row0] = ra0.z; As[nxt][a_c4 + 3][a_row0] = ra0.w;
            As[nxt][a_c4 + 0][a_row1] = ra1.x; As[nxt][a_c4 + 1][a_row1] = ra1.y;
            As[nxt][a_c4 + 2][a_row1] = ra1.z; As[nxt][a_c4 + 3][a_row1] = ra1.w;
            *(float4*)&Bs[nxt][b_k0][b_n4] = rb0;
            *(float4*)&Bs[nxt][b_k1][b_n4] = rb1;
            __syncthreads();
        }
    }

#pragma unroll
    for (int ih = 0; ih < 2; ih++) {
#pragma unroll
        for (int ii = 0; ii < 4; ii++) {
            int i = ih * 4 + ii;
            int m = m0 + (ty << 2) + ii + ih * 64;
#pragma unroll
            for (int jh = 0; jh < 2; jh++) {
                int n = n0 + (tx << 2) + jh * 64;
                float2 lo = unpack2(acc2[i][jh * 2 + 0]);
                float2 hi = unpack2(acc2[i][jh * 2 + 1]);
                float4 bb = *(const float4*)(bias + n);
                float4 v;
                v.x = lo.x + bb.x; v.y = lo.y + bb.y;
                v.z = hi.x + bb.z; v.w = hi.y + bb.w;
                if (RELU_ADD) {
                    float4 r = *(const float4*)(Rp + (size_t)m * DM + n);
                    v.x = r.x + fmaxf(v.x, 0.f);
                    v.y = r.y + fmaxf(v.y, 0.f);
                    v.z = r.z + fmaxf(v.z, 0.f);
                    v.w = r.w + fmaxf(v.w, 0.f);
                }
                *(float4*)(C + (size_t)m * DM + n) = v;
            }
        }
    }
}

// Fused QKV projections: blockIdx.z selects {Q@Wq->Qh, K@Wk->Kh, K@Wv->Vh}.
// One launch of 768 CTAs instead of 3x256 -> better wave packing.
__global__ __launch_bounds__(256)
void gemm_qkv(const float* __restrict__ Q, const float* __restrict__ K,
              const float* __restrict__ Wq, const float* __restrict__ bq,
              const float* __restrict__ Wk, const float* __restrict__ bk,
              const float* __restrict__ Wv, const float* __restrict__ bv,
              float* __restrict__ Qh, float* __restrict__ Kh,
              float* __restrict__ Vh)
{
    const int n0 = blockIdx.x * 128;
    const int m0 = blockIdx.y * 128;
    const int z  = blockIdx.z;
    const float* A = (z == 0) ? Q : K;
    const float* W = (z == 0) ? Wq : (z == 1) ? Wk : Wv;
    const float* bias = (z == 0) ? bq : (z == 1) ? bk : bv;
    float* C = (z == 0) ? Qh : (z == 1) ? Kh : Vh;
    gemm_body<false>(A, W, bias, nullptr, C, n0, m0);
}

// FFN GEMM with fused residual + relu epilogue.
__global__ __launch_bounds__(256)
void gemm_ffn(const float* __restrict__ A, const float* __restrict__ W,
              const float* __restrict__ bias, const float* __restrict__ Rp,
              float* __restrict__ C)
{
    gemm_body<true>(A, W, bias, Rp, C, blockIdx.x * 128, blockIdx.y * 128);
}

// ============================================================================
// Flash attention: per (b, h, q-tile of 64). K processed in chunks of 64.
// DYNAMIC shared memory (68,608 B > 48KB static limit) with manual layout.
// 4x4 micro-tiles; K tile row-natural [j][c] (coalesced LDG, float4 LDS
// broadcast in S phase). Register prefetch of next K/V chunk.
// Online softmax; masked keys contribute exactly 0 (matches ref's -1e12 +
// post-softmax mask-multiply, since exp underflows to 0 in fp32).
// ============================================================================
#define QT 64
#define KT 64
#define NKC (LK / KT)     // 32

// dynamic smem layout (floats):
//   Qt  [HD][QT]   : [0      , 4096 )
//   Ks  [KT][68]   : [4096   , 8448 )   row stride 68 (272B, 16B-mult)
//   Vs  [KT][HD]   : [8448   , 12544)
//   Pt  [KT][QT]   : [12544  , 16640)
//   m_s [QT]       : [16640  , 16704)
//   l_s [QT]       : [16704  , 16768)
//   alpha_s [QT]   : [16768  , 16832)
//   red [4*QT]     : [16832  , 17088)
//   maskf [KT]     : [17088  , 17152)
#define FA_SMEM_FLOATS 17152
#define FA_SMEM_BYTES  (FA_SMEM_FLOATS * 4)     // 68608

__global__ __launch_bounds__(256, 2)
void flash_attn(const float* __restrict__ Qh, const float* __restrict__ Kh,
                const float* __restrict__ Vh, const int* __restrict__ pmask,
                float* __restrict__ O)
{
    extern __shared__ float sm[];
    float (*Qt)[QT] = (float(*)[QT])(sm);            // [c][i]
    float (*Ks)[68] = (float(*)[68])(sm + 4096);     // [j][c]
    float (*Vs)[HD] = (float(*)[HD])(sm + 8448);     // [j][col]
    float (*Pt)[QT] = (float(*)[QT])(sm + 12544);    // [j][i]
    float* m_s     = sm + 16640;
    float* l_s     = sm + 16704;
    float* alpha_s = sm + 16768;
    float* red     = sm + 16832;
    float* maskf   = sm + 17088;

    const int qt  = blockIdx.x;       // 0..31
    const int h   = blockIdx.y;       // 0..7
    const int b   = blockIdx.z;       // 0..3
    const int tid = threadIdx.x;

    const float scale = 0.04419417382415922f;   // 1/sqrt(512)
    const int q0 = qt * QT;

    const float* Qb = Qh + ((size_t)(b * LQ + q0)) * DM + h * HD;
    const float* Kb = Kh + ((size_t)b * LK) * DM + h * HD;
    const float* Vb = Vh + ((size_t)b * LK) * DM + h * HD;
    const int*   mb = pmask + b * LK;

    // load Q tile transposed (one-time)
#pragma unroll
    for (int rep = 0; rep < 4; rep++) {
        int id = tid + 256 * rep;           // 0..1023
        int i  = id & 63;
        int c4 = (id >> 6) << 2;
        float4 v = *(const float4*)(Qb + (size_t)i * DM + c4);
        Qt[c4 + 0][i] = v.x; Qt[c4 + 1][i] = v.y;
        Qt[c4 + 2][i] = v.z; Qt[c4 + 3][i] = v.w;
    }
    if (tid < QT) { m_s[tid] = -1e30f; l_s[tid] = 0.f; }

    ull o2[4][2];
#pragma unroll
    for (int i = 0; i < 4; i++) { o2[i][0] = 0ull; o2[i][1] = 0ull; }

    const int tx = tid & 15, ty = tid >> 4;     // S: i=4tx, j=4ty | PV: col=4tx, row=4ty
    const int r  = tid & 63, qq = tid >> 6;     // softmax: r fast across lanes

    // chunk-load geometry (coalesced: lanes vary c fastest)
    const int lj = tid >> 4;                    // row within chunk (+16 per rep)
    const int lc = (tid & 15) << 2;             // col group

    // prefetch chunk 0
    float4 rk[4], rv[4]; float mreg = 0.f;
#pragma unroll
    for (int rep = 0; rep < 4; rep++) {
        int j = lj + rep * 16;
        rk[rep] = *(const float4*)(Kb + (size_t)j * DM + lc);
        rv[rep] = *(const float4*)(Vb + (size_t)j * DM + lc);
    }
    if (tid < KT) mreg = (mb[tid] != 0) ? 1.f : 0.f;

    for (int kc = 0; kc < NKC; kc++) {
        __syncthreads();                         // prior PV reads done
#pragma unroll
        for (int rep = 0; rep < 4; rep++) {
            int j = lj + rep * 16;
            *(float4*)&Ks[j][lc] = rk[rep];
            *(float4*)&Vs[j][lc] = rv[rep];
        }
        if (tid < KT) maskf[tid] = mreg;
        __syncthreads();

        // prefetch next chunk (overlaps all compute below)
        if (kc + 1 < NKC) {
            const float* Kn = Kb + (size_t)(kc + 1) * KT * DM;
            const float* Vn = Vb + (size_t)(kc + 1) * KT * DM;
#pragma unroll
            for (int rep = 0; rep < 4; rep++) {
                int j = lj + rep * 16;
                rk[rep] = *(const float4*)(Kn + (size_t)j * DM + lc);
                rv[rep] = *(const float4*)(Vn + (size_t)j * DM + lc);
            }
            if (tid < KT) mreg = (mb[(kc + 1) * KT + tid] != 0) ? 1.f : 0.f;
        }

        // ---- S = Q K^T : 4(i,packed) x 4(j) per thread, 4 c's per step ----
        ull s2[4][2];
#pragma unroll
        for (int jj = 0; jj < 4; jj++) { s2[jj][0] = 0ull; s2[jj][1] = 0ull; }
#pragma unroll 4
        for (int c4 = 0; c4 < HD; c4 += 4) {
            ull a[4][2];
#pragma unroll
            for (int cc = 0; cc < 4; cc++) {
                const ull* ap = (const ull*)&Qt[c4 + cc][tx << 2];
                a[cc][0] = ap[0]; a[cc][1] = ap[1];
            }
#pragma unroll
            for (int jj = 0; jj < 4; jj++) {
                float4 kq = *(const float4*)&Ks[(ty << 2) + jj][c4];  // 1 LDS.128 bcast
                ull k0 = pack2(kq.x, kq.x), k1 = pack2(kq.y, kq.y);
                ull k2 = pack2(kq.z, kq.z), k3 = pack2(kq.w, kq.w);
                fma2(s2[jj][0], k0, a[0][0]); fma2(s2[jj][1], k0, a[0][1]);
                fma2(s2[jj][0], k1, a[1][0]); fma2(s2[jj][1], k1, a[1][1]);
                fma2(s2[jj][0], k2, a[2][0]); fma2(s2[jj][1], k2, a[2][1]);
                fma2(s2[jj][0], k3, a[3][0]); fma2(s2[jj][1], k3, a[3][1]);
            }
        }
#pragma unroll
        for (int jj = 0; jj < 4; jj++) {
            int j = (ty << 2) + jj;
            float mv = maskf[j];
            float2 p01 = unpack2(s2[jj][0]);
            float2 p23 = unpack2(s2[jj][1]);
            float4 w;
            w.x = (mv > 0.f) ? p01.x * scale : -1e30f;
            w.y = (mv > 0.f) ? p01.y * scale : -1e30f;
            w.z = (mv > 0.f) ? p23.x * scale : -1e30f;
            w.w = (mv > 0.f) ? p23.y * scale : -1e30f;
            *(float4*)&Pt[j][tx << 2] = w;
        }
        __syncthreads();

        // ---- online softmax: thread handles keys qq*16..qq*16+15 of row r ----
        float pm = -1e30f;
#pragma unroll
        for (int t = 0; t < 16; t++) pm = fmaxf(pm, Pt[qq * 16 + t][r]);
        red[qq * QT + r] = pm;
        __syncthreads();
        if (qq == 0) {
            float m4 = fmaxf(fmaxf(red[r], red[QT + r]),
                             fmaxf(red[2 * QT + r], red[3 * QT + r]));
            float mn = fmaxf(m_s[r], m4);
            alpha_s[r] = __expf(m_s[r] - mn);
            m_s[r] = mn;
        }
        __syncthreads();
        {
            float mn = m_s[r];
            float ps = 0.f;
#pragma unroll
            for (int t = 0; t < 16; t++) {
                int j = qq * 16 + t;
                float p = __expf(Pt[j][r] - mn) * maskf[j];
                Pt[j][r] = p;
                ps += p;
            }
            red[qq * QT + r] = ps;
        }
        __syncthreads();
        if (qq == 0)
            l_s[r] = l_s[r] * alpha_s[r] +
                     (red[r] + red[QT + r]) + (red[2 * QT + r] + red[3 * QT + r]);

        // ---- O = O*alpha + P @ V ----
#pragma unroll
        for (int ii = 0; ii < 4; ii++) {
            float a = alpha_s[(ty << 2) + ii];
            ull a2 = pack2(a, a);
            mul2(o2[ii][0], a2); mul2(o2[ii][1], a2);
        }
#pragma unroll 8
        for (int j = 0; j < KT; j++) {
            float4 p = *(const float4*)&Pt[j][ty << 2];   // near-broadcast
            const ull* vp = (const ull*)&Vs[j][tx << 2];
            ull v01 = vp[0], v23 = vp[1];
            ull p0 = pack2(p.x, p.x), p1 = pack2(p.y, p.y);
            ull p2 = pack2(p.z, p.z), p3 = pack2(p.w, p.w);
            fma2(o2[0][0], p0, v01); fma2(o2[0][1], p0, v23);
            fma2(o2[1][0], p1, v01); fma2(o2[1][1], p1, v23);
            fma2(o2[2][0], p2, v01); fma2(o2[2][1], p2, v23);
            fma2(o2[3][0], p3, v01); fma2(o2[3][1], p3, v23);
        }
    }
    __syncthreads();   // l_s final visibility

    float* Ob = O + ((size_t)(b * LQ + q0)) * DM + h * HD;
#pragma unroll
    for (int ii = 0; ii < 4; ii++) {
        float l = l_s[(ty << 2) + ii];
        float inv = (l > 0.f) ? 1.f / l : 0.f;
        float2 lo = unpack2(o2[ii][0]);
        float2 hi = unpack2(o2[ii][1]);
        float4 v = make_float4(lo.x * inv, lo.y * inv, hi.x * inv, hi.y * inv);
        *(float4*)(Ob + (size_t)((ty << 2) + ii) * DM + (tx << 2)) = v;
    }
}

// ============================================================================
// LayerNorm over 512, optional residual input R (row-wise x = X + R).
// One block (128 threads) per row.
// ============================================================================
__global__ __launch_bounds__(128)
void ln512(const float* __restrict__ X, const float* __restrict__ R,
           const float* __restrict__ g, const float* __restrict__ bta,
           float* __restrict__ out)
{
    const int row = blockIdx.x;
    const int tid = threadIdx.x;
    const size_t base = (size_t)row * DM + tid * 4;

    float4 x = *(const float4*)(X + base);
    if (R) {
        float4 rr = *(const float4*)(R + base);
        x.x += rr.x; x.y += rr.y; x.z += rr.z; x.w += rr.w;
    }
    float s  = x.x + x.y + x.z + x.w;
    float s2 = x.x * x.x + x.y * x.y + x.z * x.z + x.w * x.w;
#pragma unroll
    for (int off = 16; off; off >>= 1) {
        s  += __shfl_xor_sync(0xFFFFFFFFu, s,  off);
        s2 += __shfl_xor_sync(0xFFFFFFFFu, s2, off);
    }
    __shared__ float ss[4], ss2[4];
    if ((tid & 31) == 0) { ss[tid >> 5] = s; ss2[tid >> 5] = s2; }
    __syncthreads();
    s  = ss[0] + ss[1] + ss[2] + ss[3];
    s2 = ss2[0] + ss2[1] + ss2[2] + ss2[3];

    const float mu   = s * (1.f / DM);
    const float var  = s2 * (1.f / DM) - mu * mu;
    const float rstd = rsqrtf(var + 1e-5f);

    float4 gg = *(const float4*)(g + tid * 4);
    float4 bb = *(const float4*)(bta + tid * 4);
    float4 v;
    v.x = (x.x - mu) * rstd * gg.x + bb.x;
    v.y = (x.y - mu) * rstd * gg.y + bb.y;
    v.z = (x.z - mu) * rstd * gg.z + bb.z;
    v.w = (x.w - mu) * rstd * gg.w + bb.w;
    *(float4*)(out + base) = v;
}

// ============================================================================
// Launch
// ============================================================================
extern "C" void kernel_launch(void* const* d_in, const int* in_sizes, int n_in,
                              void* d_out, int out_size)
{
    const float* Q   = (const float*)d_in[0];
    const float* K   = (const float*)d_in[1];
    const int*   pad = (const int*)  d_in[2];
    const float* Wq  = (const float*)d_in[3];
    const float* bq  = (const float*)d_in[4];
    const float* Wk  = (const float*)d_in[5];
    const float* bk  = (const float*)d_in[6];
    const float* Wv  = (const float*)d_in[7];
    const float* bv  = (const float*)d_in[8];
    const float* Wo  = (const float*)d_in[9];
    const float* bo  = (const float*)d_in[10];
    const float* g0  = (const float*)d_in[11];
    const float* b0  = (const float*)d_in[12];
    const float* g1  = (const float*)d_in[13];
    const float* b1  = (const float*)d_in[14];
    float* out = (float*)d_out;

    float *Qh, *Kh, *Vh, *At;
    cudaGetSymbolAddress((void**)&Qh, g_Qh);
    cudaGetSymbolAddress((void**)&Kh, g_Kh);
    cudaGetSymbolAddress((void**)&Vh, g_Vh);
    cudaGetSymbolAddress((void**)&At, g_At);

    // opt-in to >48KB dynamic smem for flash_attn (attribute set, not an
    // allocation; not a stream op -> graph-capture-safe, idempotent)
    cudaFuncSetAttribute(flash_attn,
                         cudaFuncAttributeMaxDynamicSharedMemorySize,
                         FA_SMEM_BYTES);

    // fused QKV projections: one launch, 768 CTAs
    dim3 qkvgrid(DM / 128, NROWS / 128, 3);   // (4, 64, 3)
    gemm_qkv<<<qkvgrid, 256>>>(Q, K, Wq, bq, Wk, bk, Wv, bv, Qh, Kh, Vh);

    // attention
    dim3 fgrid(LQ / QT, NH, NB);              // (32, 8, 4)
    flash_attn<<<fgrid, 256, FA_SMEM_BYTES>>>(Qh, Kh, Vh, pad, At);

    // T = LN0(Q + attn)   (Qh free after attention -> reuse as T)
    ln512<<<NROWS, 128>>>(At, Q, g0, b0, Qh);

    // U = T + relu(T @ Wo + bo)   (Kh free -> reuse)
    dim3 ggrid(DM / 128, NROWS / 128);        // (4, 64)
    gemm_ffn<<<ggrid, 256>>>(Qh, Wo, bo, Qh, Kh);

    // out = LN1(U)
    ln512<<<NROWS, 128>>>(Kh, nullptr, g1, b1, out);
}

// round 12
// speedup vs baseline: 1.8534x; 1.8534x over previous
#include <cuda_runtime.h>
#include <cuda_bf16.h>
#include <math.h>
#include <stdint.h>

// Problem: MAB_37409165148591
// B=4, LQ=LK=2048, D=512, H=8, head_dim=64
// out = LN1( T + relu(T@Wo+bo) ),  T = LN0( Q + Attn(Q@Wq+bq, K@Wk+bk, K@Wv+bv, pad_mask) )

#define NB 4
#define LQ 2048
#define LK 2048
#define DM 512
#define NH 8
#define HD 64
#define NROWS (NB * LQ)          // 8192
#define NEL   (NROWS * DM)       // 4194304

// ---- tf32 helpers ----
__device__ __forceinline__ float tf32r(float x) {      // round fp32 -> tf32 bits
    uint32_t r; asm("cvt.rna.tf32.f32 %0, %1;" : "=r"(r) : "f"(x));
    return __uint_as_float(r);
}
__device__ __forceinline__ void mma_tf32(float* c,
                                         uint32_t a0, uint32_t a1,
                                         uint32_t a2, uint32_t a3,
                                         uint32_t b0, uint32_t b1) {
    asm volatile(
        "mma.sync.aligned.m16n8k8.row.col.f32.tf32.tf32.f32 "
        "{%0,%1,%2,%3}, {%4,%5,%6,%7}, {%8,%9}, {%0,%1,%2,%3};"
        : "+f"(c[0]), "+f"(c[1]), "+f"(c[2]), "+f"(c[3])
        : "r"(a0), "r"(a1), "r"(a2), "r"(a3), "r"(b0), "r"(b1));
}

// ---- scratch (static device globals; no allocation allowed) ----
__device__ float g_Qh[NEL];
__device__ float g_Kh[NEL];
__device__ float g_Vh[NEL];
__device__ float g_At[NEL];

// ============================================================================
// GEMM body (tf32 tensor cores): C[8192,512] = A @ W + bias,
// optional (res + relu(.)). 128x128 tile, BK=16, 256 threads (8 warps, 2Mx4N),
// warp tile 64x32 via m16n8k8 mma.sync. Inputs tf32-rounded at staging.
// Double-buffered smem, one __syncthreads per k-block.
// ============================================================================
template<bool RELU_ADD>
__device__ __forceinline__
void gemm_body(const float* __restrict__ A, const float* __restrict__ W,
               const float* __restrict__ bias, const float* __restrict__ Rp,
               float* __restrict__ C, int n0, int m0)
{
    __shared__ float As[2][16][132];   // [stage][k][m] (tf32-rounded values)
    __shared__ float Bs[2][16][132];   // [stage][k][n]

    const int tid  = threadIdx.x;
    const int wid  = tid >> 5, lane = tid & 31;
    const int grp  = lane >> 2, tig = lane & 3;
    const int wm   = (wid >> 2) << 6;      // warp M offset: 0,64
    const int wn   = (wid & 3) << 5;       // warp N offset: 0,32,64,96

    const int a_row0 = tid >> 2,           a_c4 = (tid & 3) << 2;
    const int a_row1 = (tid + 256) >> 2;
    const int b_k0 = tid >> 5,             b_n4 = (tid & 31) << 2;
    const int b_k1 = (tid + 256) >> 5;

    const float* Arow0 = A + (size_t)(m0 + a_row0) * DM + a_c4;
    const float* Arow1 = A + (size_t)(m0 + a_row1) * DM + a_c4;
    const float* Wrow0 = W + (size_t)b_k0 * DM + n0 + b_n4;
    const float* Wrow1 = W + (size_t)b_k1 * DM + n0 + b_n4;

    float acc[4][4][4];
#pragma unroll
    for (int mt = 0; mt < 4; mt++)
#pragma unroll
        for (int nt = 0; nt < 4; nt++)
#pragma unroll
            for (int q = 0; q < 4; q++) acc[mt][nt][q] = 0.f;

    float4 ra0 = *(const float4*)(Arow0);
    float4 ra1 = *(const float4*)(Arow1);
    float4 rb0 = *(const float4*)(Wrow0);
    float4 rb1 = *(const float4*)(Wrow1);
    As[0][a_c4 + 0][a_row0] = tf32r(ra0.x); As[0][a_c4 + 1][a_row0] = tf32r(ra0.y);
    As[0][a_c4 + 2][a_row0] = tf32r(ra0.z); As[0][a_c4 + 3][a_row0] = tf32r(ra0.w);
    As[0][a_c4 + 0][a_row1] = tf32r(ra1.x); As[0][a_c4 + 1][a_row1] = tf32r(ra1.y);
    As[0][a_c4 + 2][a_row1] = tf32r(ra1.z); As[0][a_c4 + 3][a_row1] = tf32r(ra1.w);
    *(float4*)&Bs[0][b_k0][b_n4] =
        make_float4(tf32r(rb0.x), tf32r(rb0.y), tf32r(rb0.z), tf32r(rb0.w));
    *(float4*)&Bs[0][b_k1][b_n4] =
        make_float4(tf32r(rb1.x), tf32r(rb1.y), tf32r(rb1.z), tf32r(rb1.w));
    __syncthreads();

#pragma unroll 1
    for (int blk = 0; blk < DM / 16; blk++) {
        const int cur = blk & 1;
        const int nxt = cur ^ 1;
        const int kb_next = (blk + 1) * 16;

        if (kb_next < DM) {
            ra0 = *(const float4*)(Arow0 + kb_next);
            ra1 = *(const float4*)(Arow1 + kb_next);
            rb0 = *(const float4*)(Wrow0 + (size_t)kb_next * DM);
            rb1 = *(const float4*)(Wrow1 + (size_t)kb_next * DM);
        }

        const float (*Asl)[132] = As[cur];
        const float (*Bsl)[132] = Bs[cur];
#pragma unroll
        for (int ks = 0; ks < 2; ks++) {
            const int k0 = ks << 3;
            uint32_t af[4][4], bf[4][2];
#pragma unroll
            for (int mt = 0; mt < 4; mt++) {
                int row = wm + (mt << 4) + grp;
                af[mt][0] = __float_as_uint(Asl[k0 + tig][row]);
                af[mt][1] = __float_as_uint(Asl[k0 + tig][row + 8]);
                af[mt][2] = __float_as_uint(Asl[k0 + tig + 4][row]);
                af[mt][3] = __float_as_uint(Asl[k0 + tig + 4][row + 8]);
            }
#pragma unroll
            for (int nt = 0; nt < 4; nt++) {
                int col = wn + (nt << 3) + grp;
                bf[nt][0] = __float_as_uint(Bsl[k0 + tig][col]);
                bf[nt][1] = __float_as_uint(Bsl[k0 + tig + 4][col]);
            }
#pragma unroll
            for (int mt = 0; mt < 4; mt++)
#pragma unroll
                for (int nt = 0; nt < 4; nt++)
                    mma_tf32(acc[mt][nt],
                             af[mt][0], af[mt][1], af[mt][2], af[mt][3],
                             bf[nt][0], bf[nt][1]);
        }

        if (kb_next < DM) {
            As[nxt][a_c4 + 0][a_row0] = tf32r(ra0.x); As[nxt][a_c4 + 1][a_row0] = tf32r(ra0.y);
            As[nxt][a_c4 + 2][a_row0] = tf32r(ra0.z); As[nxt][a_c4 + 3][a_row0] = tf32r(ra0.w);
            As[nxt][a_c4 + 0][a_row1] = tf32r(ra1.x); As[nxt][a_c4 + 1][a_row1] = tf32r(ra1.y);
            As[nxt][a_c4 + 2][a_row1] = tf32r(ra1.z); As[nxt][a_c4 + 3][a_row1] = tf32r(ra1.w);
            *(float4*)&Bs[nxt][b_k0][b_n4] =
                make_float4(tf32r(rb0.x), tf32r(rb0.y), tf32r(rb0.z), tf32r(rb0.w));
            *(float4*)&Bs[nxt][b_k1][b_n4] =
                make_float4(tf32r(rb1.x), tf32r(rb1.y), tf32r(rb1.z), tf32r(rb1.w));
            __syncthreads();
        }
    }

#pragma unroll
    for (int mt = 0; mt < 4; mt++) {
#pragma unroll
        for (int nt = 0; nt < 4; nt++) {
            int row0 = m0 + wm + (mt << 4) + grp;
            int row1 = row0 + 8;
            int col  = n0 + wn + (nt << 3) + (tig << 1);
            float2 bb = *(const float2*)(bias + col);
            float2 v0, v1;
            v0.x = acc[mt][nt][0] + bb.x; v0.y = acc[mt][nt][1] + bb.y;
            v1.x = acc[mt][nt][2] + bb.x; v1.y = acc[mt][nt][3] + bb.y;
            if (RELU_ADD) {
                float2 r0 = *(const float2*)(Rp + (size_t)row0 * DM + col);
                float2 r1 = *(const float2*)(Rp + (size_t)row1 * DM + col);
                v0.x = r0.x + fmaxf(v0.x, 0.f); v0.y = r0.y + fmaxf(v0.y, 0.f);
                v1.x = r1.x + fmaxf(v1.x, 0.f); v1.y = r1.y + fmaxf(v1.y, 0.f);
            }
            *(float2*)(C + (size_t)row0 * DM + col) = v0;
            *(float2*)(C + (size_t)row1 * DM + col) = v1;
        }
    }
}

__global__ __launch_bounds__(256, 2)
void gemm_qkv(const float* __restrict__ Q, const float* __restrict__ K,
              const float* __restrict__ Wq, const float* __restrict__ bq,
              const float* __restrict__ Wk, const float* __restrict__ bk,
              const float* __restrict__ Wv, const float* __restrict__ bv,
              float* __restrict__ Qh, float* __restrict__ Kh,
              float* __restrict__ Vh)
{
    const int n0 = blockIdx.x * 128;
    const int m0 = blockIdx.y * 128;
    const int z  = blockIdx.z;
    const float* A = (z == 0) ? Q : K;
    const float* W = (z == 0) ? Wq : (z == 1) ? Wk : Wv;
    const float* bias = (z == 0) ? bq : (z == 1) ? bk : bv;
    float* C = (z == 0) ? Qh : (z == 1) ? Kh : Vh;
    gemm_body<false>(A, W, bias, nullptr, C, n0, m0);
}

__global__ __launch_bounds__(256, 2)
void gemm_ffn(const float* __restrict__ A, const float* __restrict__ W,
              const float* __restrict__ bias, const float* __restrict__ Rp,
              float* __restrict__ C)
{
    gemm_body<true>(A, W, bias, Rp, C, blockIdx.x * 128, blockIdx.y * 128);
}

// ============================================================================
// Flash attention (tf32 tensor cores): per (b, h, q-tile of 64), K chunks of 64.
// 8 warps = 2(M) x 4(N); warp tile 32x16 via m16n8k8. All tiles row-natural
// stride-68 smem ([row][c]); Q/K/V/P tf32-rounded; softmax fp32 in smem.
// Masked keys contribute exactly 0 (matches ref's -1e12 + post-softmax
// mask-multiply, since exp underflows to 0 in fp32).
// ============================================================================
#define QT 64
#define KT 64
#define NKC (LK / KT)     // 32

// dynamic smem layout (floats):
//   Qs [64][68] : 0..4352      (row-natural, tf32-rounded)
//   Ks [64][68] : 4352..8704
//   Vs [64][68] : 8704..13056
//   Pt [64][68] : 13056..17408 ([j][i], stride 68)
//   m_s[64] 17408  l_s[64] 17472  alpha_s[64] 17536
//   red[256] 17600  maskf[64] 17856   -> total 17920 floats
#define FA_SMEM_FLOATS 17920
#define FA_SMEM_BYTES  (FA_SMEM_FLOATS * 4)     // 71680

__global__ __launch_bounds__(256, 2)
void flash_attn(const float* __restrict__ Qh, const float* __restrict__ Kh,
                const float* __restrict__ Vh, const int* __restrict__ pmask,
                float* __restrict__ O)
{
    extern __shared__ float sm[];
    float (*Qs)[68] = (float(*)[68])(sm);
    float (*Ks)[68] = (float(*)[68])(sm + 4352);
    float (*Vs)[68] = (float(*)[68])(sm + 8704);
    float (*Pt)[68] = (float(*)[68])(sm + 13056);
    float* m_s     = sm + 17408;
    float* l_s     = sm + 17472;
    float* alpha_s = sm + 17536;
    float* red     = sm + 17600;
    float* maskf   = sm + 17856;

    const int qt  = blockIdx.x;
    const int h   = blockIdx.y;
    const int b   = blockIdx.z;
    const int tid = threadIdx.x;
    const int wid = tid >> 5, lane = tid & 31;
    const int grp = lane >> 2, tig = lane & 3;
    const int wm  = (wid >> 2) << 5;    // 0,32
    const int wn  = (wid & 3) << 4;     // 0,16,32,48

    const float scale = 0.04419417382415922f;   // 1/sqrt(512)
    const int q0 = qt * QT;

    const float* Qb = Qh + ((size_t)(b * LQ + q0)) * DM + h * HD;
    const float* Kb = Kh + ((size_t)b * LK) * DM + h * HD;
    const float* Vb = Vh + ((size_t)b * LK) * DM + h * HD;
    const int*   mb = pmask + b * LK;

    // staging geometry (coalesced: lanes vary c fastest)
    const int lj = tid >> 4;            // row within tile (+16 per rep)
    const int lc = (tid & 15) << 2;     // col group

    // load Q tile row-natural, tf32-rounded (one-time)
#pragma unroll
    for (int rep = 0; rep < 4; rep++) {
        int row = lj + rep * 16;
        float4 v = *(const float4*)(Qb + (size_t)row * DM + lc);
        Qs[row][lc + 0] = tf32r(v.x); Qs[row][lc + 1] = tf32r(v.y);
        Qs[row][lc + 2] = tf32r(v.z); Qs[row][lc + 3] = tf32r(v.w);
    }
    if (tid < QT) { m_s[tid] = -1e30f; l_s[tid] = 0.f; }

    float oacc[2][2][4];
#pragma unroll
    for (int mt = 0; mt < 2; mt++)
#pragma unroll
        for (int nt = 0; nt < 2; nt++)
#pragma unroll
            for (int q = 0; q < 4; q++) oacc[mt][nt][q] = 0.f;

    const int r = tid & 63, qq = tid >> 6;     // softmax mapping

    // prefetch chunk 0
    float4 rk[4], rv[4]; float mreg = 0.f;
#pragma unroll
    for (int rep = 0; rep < 4; rep++) {
        int j = lj + rep * 16;
        rk[rep] = *(const float4*)(Kb + (size_t)j * DM + lc);
        rv[rep] = *(const float4*)(Vb + (size_t)j * DM + lc);
    }
    if (tid < KT) mreg = (mb[tid] != 0) ? 1.f : 0.f;

    for (int kc = 0; kc < NKC; kc++) {
        __syncthreads();                 // prior PV reads done
#pragma unroll
        for (int rep = 0; rep < 4; rep++) {
            int j = lj + rep * 16;
            Ks[j][lc + 0] = tf32r(rk[rep].x); Ks[j][lc + 1] = tf32r(rk[rep].y);
            Ks[j][lc + 2] = tf32r(rk[rep].z); Ks[j][lc + 3] = tf32r(rk[rep].w);
            Vs[j][lc + 0] = tf32r(rv[rep].x); Vs[j][lc + 1] = tf32r(rv[rep].y);
            Vs[j][lc + 2] = tf32r(rv[rep].z); Vs[j][lc + 3] = tf32r(rv[rep].w);
        }
        if (tid < KT) maskf[tid] = mreg;
        __syncthreads();

        // prefetch next chunk (overlaps compute below)
        if (kc + 1 < NKC) {
            const float* Kn = Kb + (size_t)(kc + 1) * KT * DM;
            const float* Vn = Vb + (size_t)(kc + 1) * KT * DM;
#pragma unroll
            for (int rep = 0; rep < 4; rep++) {
                int j = lj + rep * 16;
                rk[rep] = *(const float4*)(Kn + (size_t)j * DM + lc);
                rv[rep] = *(const float4*)(Vn + (size_t)j * DM + lc);
            }
            if (tid < KT) mreg = (mb[(kc + 1) * KT + tid] != 0) ? 1.f : 0.f;
        }

        // ---- S = Q K^T via mma: warp tile 32(M) x 16(N), 8 k-steps ----
        float sacc[2][2][4];
#pragma unroll
        for (int mt = 0; mt < 2; mt++)
#pragma unroll
            for (int nt = 0; nt < 2; nt++)
#pragma unroll
                for (int q = 0; q < 4; q++) sacc[mt][nt][q] = 0.f;

#pragma unroll
        for (int ks = 0; ks < 8; ks++) {
            const int k0 = ks << 3;
            uint32_t af[2][4], bf[2][2];
#pragma unroll
            for (int mt = 0; mt < 2; mt++) {
                int row = wm + (mt << 4) + grp;
                af[mt][0] = __float_as_uint(Qs[row][k0 + tig]);
                af[mt][1] = __float_as_uint(Qs[row + 8][k0 + tig]);
                af[mt][2] = __float_as_uint(Qs[row][k0 + tig + 4]);
                af[mt][3] = __float_as_uint(Qs[row + 8][k0 + tig + 4]);
            }
#pragma unroll
            for (int nt = 0; nt < 2; nt++) {
                int j = wn + (nt << 3) + grp;
                bf[nt][0] = __float_as_uint(Ks[j][k0 + tig]);
                bf[nt][1] = __float_as_uint(Ks[j][k0 + tig + 4]);
            }
#pragma unroll
            for (int mt = 0; mt < 2; mt++)
#pragma unroll
                for (int nt = 0; nt < 2; nt++)
                    mma_tf32(sacc[mt][nt],
                             af[mt][0], af[mt][1], af[mt][2], af[mt][3],
                             bf[nt][0], bf[nt][1]);
        }

        // mask + scale -> Pt[j][i] (conflict-free: bank = 8*tig+grp)
#pragma unroll
        for (int mt = 0; mt < 2; mt++) {
            int row = wm + (mt << 4) + grp;
#pragma unroll
            for (int nt = 0; nt < 2; nt++) {
                int j0 = wn + (nt << 3) + (tig << 1);
                int j1 = j0 + 1;
                bool m0v = maskf[j0] > 0.f, m1v = maskf[j1] > 0.f;
                Pt[j0][row]     = m0v ? sacc[mt][nt][0] * scale : -1e30f;
                Pt[j1][row]     = m1v ? sacc[mt][nt][1] * scale : -1e30f;
                Pt[j0][row + 8] = m0v ? sacc[mt][nt][2] * scale : -1e30f;
                Pt[j1][row + 8] = m1v ? sacc[mt][nt][3] * scale : -1e30f;
            }
        }
        __syncthreads();

        // ---- online softmax: thread covers keys qq*16..+15 of row r ----
        float pm = -1e30f;
#pragma unroll
        for (int t = 0; t < 16; t++) pm = fmaxf(pm, Pt[qq * 16 + t][r]);
        red[qq * QT + r] = pm;
        __syncthreads();
        if (qq == 0) {
            float m4 = fmaxf(fmaxf(red[r], red[QT + r]),
                             fmaxf(red[2 * QT + r], red[3 * QT + r]));
            float mn = fmaxf(m_s[r], m4);
            alpha_s[r] = __expf(m_s[r] - mn);
            m_s[r] = mn;
        }
        __syncthreads();
        {
            float mn = m_s[r];
            float ps = 0.f;
#pragma unroll
            for (int t = 0; t < 16; t++) {
                int j = qq * 16 + t;
                float p = __expf(Pt[j][r] - mn) * maskf[j];
                Pt[j][r] = tf32r(p);          // rounded for the PV mma
                ps += p;
            }
            red[qq * QT + r] = ps;
        }
        __syncthreads();
        if (qq == 0)
            l_s[r] = l_s[r] * alpha_s[r] +
                     (red[r] + red[QT + r]) + (red[2 * QT + r] + red[3 * QT + r]);

        // ---- O = O*alpha + P @ V via mma ----
#pragma unroll
        for (int mt = 0; mt < 2; mt++) {
            int row = wm + (mt << 4) + grp;
            float a0 = alpha_s[row], a1 = alpha_s[row + 8];
#pragma unroll
            for (int nt = 0; nt < 2; nt++) {
                oacc[mt][nt][0] *= a0; oacc[mt][nt][1] *= a0;
                oacc[mt][nt][2] *= a1; oacc[mt][nt][3] *= a1;
            }
        }
#pragma unroll
        for (int ks = 0; ks < 8; ks++) {
            const int k0 = ks << 3;
            uint32_t af[2][4], bf[2][2];
#pragma unroll
            for (int mt = 0; mt < 2; mt++) {
                int row = wm + (mt << 4) + grp;
                af[mt][0] = __float_as_uint(Pt[k0 + tig][row]);
                af[mt][1] = __float_as_uint(Pt[k0 + tig][row + 8]);
                af[mt][2] = __float_as_uint(Pt[k0 + tig + 4][row]);
                af[mt][3] = __float_as_uint(Pt[k0 + tig + 4][row + 8]);
            }
#pragma unroll
            for (int nt = 0; nt < 2; nt++) {
                int col = wn + (nt << 3) + grp;
                bf[nt][0] = __float_as_uint(Vs[k0 + tig][col]);
                bf[nt][1] = __float_as_uint(Vs[k0 + tig + 4][col]);
            }
#pragma unroll
            for (int mt = 0; mt < 2; mt++)
#pragma unroll
                for (int nt = 0; nt < 2; nt++)
                    mma_tf32(oacc[mt][nt],
                             af[mt][0], af[mt][1], af[mt][2], af[mt][3],
                             bf[nt][0], bf[nt][1]);
        }
    }
    __syncthreads();   // l_s final visibility

    float* Ob = O + ((size_t)(b * LQ + q0)) * DM + h * HD;
#pragma unroll
    for (int mt = 0; mt < 2; mt++) {
        int row = wm + (mt << 4) + grp;
        float l0 = l_s[row], l1 = l_s[row + 8];
        float inv0 = (l0 > 0.f) ? 1.f / l0 : 0.f;
        float inv1 = (l1 > 0.f) ? 1.f / l1 : 0.f;
#pragma unroll
        for (int nt = 0; nt < 2; nt++) {
            int col = wn + (nt << 3) + (tig << 1);
            float2 v0 = make_float2(oacc[mt][nt][0] * inv0, oacc[mt][nt][1] * inv0);
            float2 v1 = make_float2(oacc[mt][nt][2] * inv1, oacc[mt][nt][3] * inv1);
            *(float2*)(Ob + (size_t)row * DM + col)       = v0;
            *(float2*)(Ob + (size_t)(row + 8) * DM + col) = v1;
        }
    }
}

// ============================================================================
// LayerNorm over 512, optional residual input R. One block (128 thr) per row.
// ============================================================================
__global__ __launch_bounds__(128)
void ln512(const float* __restrict__ X, const float* __restrict__ R,
           const float* __restrict__ g, const float* __restrict__ bta,
           float* __restrict__ out)
{
    const int row = blockIdx.x;
    const int tid = threadIdx.x;
    const size_t base = (size_t)row * DM + tid * 4;

    float4 x = *(const float4*)(X + base);
    if (R) {
        float4 rr = *(const float4*)(R + base);
        x.x += rr.x; x.y += rr.y; x.z += rr.z; x.w += rr.w;
    }
    float s  = x.x + x.y + x.z + x.w;
    float s2 = x.x * x.x + x.y * x.y + x.z * x.z + x.w * x.w;
#pragma unroll
    for (int off = 16; off; off >>= 1) {
        s  += __shfl_xor_sync(0xFFFFFFFFu, s,  off);
        s2 += __shfl_xor_sync(0xFFFFFFFFu, s2, off);
    }
    __shared__ float ss[4], ss2[4];
    if ((tid & 31) == 0) { ss[tid >> 5] = s; ss2[tid >> 5] = s2; }
    __syncthreads();
    s  = ss[0] + ss[1] + ss[2] + ss[3];
    s2 = ss2[0] + ss2[1] + ss2[2] + ss2[3];

    const float mu   = s * (1.f / DM);
    const float var  = s2 * (1.f / DM) - mu * mu;
    const float rstd = rsqrtf(var + 1e-5f);

    float4 gg = *(const float4*)(g + tid * 4);
    float4 bb = *(const float4*)(bta + tid * 4);
    float4 v;
    v.x = (x.x - mu) * rstd * gg.x + bb.x;
    v.y = (x.y - mu) * rstd * gg.y + bb.y;
    v.z = (x.z - mu) * rstd * gg.z + bb.z;
    v.w = (x.w - mu) * rstd * gg.w + bb.w;
    *(float4*)(out + base) = v;
}

// ============================================================================
// Launch
// ============================================================================
extern "C" void kernel_launch(void* const* d_in, const int* in_sizes, int n_in,
                              void* d_out, int out_size)
{
    const float* Q   = (const float*)d_in[0];
    const float* K   = (const float*)d_in[1];
    const int*   pad = (const int*)  d_in[2];
    const float* Wq  = (const float*)d_in[3];
    const float* bq  = (const float*)d_in[4];
    const float* Wk  = (const float*)d_in[5];
    const float* bk  = (const float*)d_in[6];
    const float* Wv  = (const float*)d_in[7];
    const float* bv  = (const float*)d_in[8];
    const float* Wo  = (const float*)d_in[9];
    const float* bo  = (const float*)d_in[10];
    const float* g0  = (const float*)d_in[11];
    const float* b0  = (const float*)d_in[12];
    const float* g1  = (const float*)d_in[13];
    const float* b1  = (const float*)d_in[14];
    float* out = (float*)d_out;

    float *Qh, *Kh, *Vh, *At;
    cudaGetSymbolAddress((void**)&Qh, g_Qh);
    cudaGetSymbolAddress((void**)&Kh, g_Kh);
    cudaGetSymbolAddress((void**)&Vh, g_Vh);
    cudaGetSymbolAddress((void**)&At, g_At);

    // opt-in to >48KB dynamic smem for flash_attn (attribute, not allocation)
    cudaFuncSetAttribute(flash_attn,
                         cudaFuncAttributeMaxDynamicSharedMemorySize,
                         FA_SMEM_BYTES);

    // fused QKV projections (tf32 tensor cores): one launch, 768 CTAs
    dim3 qkvgrid(DM / 128, NROWS / 128, 3);   // (4, 64, 3)
    gemm_qkv<<<qkvgrid, 256>>>(Q, K, Wq, bq, Wk, bk, Wv, bv, Qh, Kh, Vh);

    // attention (tf32 tensor cores)
    dim3 fgrid(LQ / QT, NH, NB);              // (32, 8, 4)
    flash_attn<<<fgrid, 256, FA_SMEM_BYTES>>>(Qh, Kh, Vh, pad, At);

    // T = LN0(Q + attn)
    ln512<<<NROWS, 128>>>(At, Q, g0, b0, Qh);

    // U = T + relu(T @ Wo + bo)  (tf32 tensor cores)
    dim3 ggrid(DM / 128, NROWS / 128);        // (4, 64)
    gemm_ffn<<<ggrid, 256>>>(Qh, Wo, bo, Qh, Kh);

    // out = LN1(U)
    ln512<<<NROWS, 128>>>(Kh, nullptr, g1, b1, out);
}